// round 16
// baseline (speedup 1.0000x reference)
#include <cuda_runtime.h>

#define Bn   16
#define Tn   262144
#define HOP  256
#define WINL 1024
#define PADL 384
#define Fn   1024
#define Pn   22
#define NCHUNK 32           // full sequence per warp: zero redundancy

typedef unsigned long long ull;

static __device__ __forceinline__ ull pk2(float lo, float hi) {
    ull r; asm("mov.b64 %0,{%1,%2};" : "=l"(r) : "f"(lo), "f"(hi)); return r;
}
static __device__ __forceinline__ void upk2(float& lo, float& hi, ull v) {
    asm("mov.b64 {%0,%1},%2;" : "=f"(lo), "=f"(hi) : "l"(v));
}
static __device__ __forceinline__ ull fma2_(ull a, ull b, ull c) {
    ull r; asm("fma.rn.f32x2 %0,%1,%2,%3;" : "=l"(r) : "l"(a), "l"(b), "l"(c)); return r;
}
static __device__ __forceinline__ ull mul2_(ull a, ull b) {
    ull r; asm("mul.rn.f32x2 %0,%1,%2;" : "=l"(r) : "l"(a), "l"(b)); return r;
}
static __device__ __forceinline__ ull add2_(ull a, ull b) {
    ull r; asm("add.rn.f32x2 %0,%1,%2;" : "=l"(r) : "l"(a), "l"(b)); return r;
}
static __device__ __forceinline__ void redadd(float* p, float v) {
    asm volatile("red.global.add.f32 [%0], %1;" :: "l"(p), "f"(v) : "memory");
}

static __device__ __forceinline__ float hannf(int t) {
    return 0.5f - 0.5f * __cosf(6.283185307179586f * (float)t * (1.0f / 1024.0f));
}

// ---------------------------------------------------------------------------
// Kernel 0: zero the output (poisoned 0xAA by harness; RED needs zeros)
// ---------------------------------------------------------------------------
__global__ void zero_kernel(float* __restrict__ out) {
    const int i = blockIdx.x * blockDim.x + threadIdx.x;
    if (i < Bn * Tn / 4)
        ((float4*)out)[i] = make_float4(0.f, 0.f, 0.f, 0.f);
}

// ---------------------------------------------------------------------------
// Kernel 1: 128 CTAs x 128 threads; warp w handles frame group 4*blk+w.
//   Zero redundancy (each lane runs its full 1024-sample sequence serially).
//   Emission: red.global.add of 0.5*w(t)*y straight into out — deletes the
//   64MB frame buffer AND the 15us gather kernel; RED is atomic -> race-free.
//   Recurrence: paired 2-sample blocks; block B's dots reuse CA/CE against
//   (P, H[0..9]) exactly, halving history-shift MOVs.
// ---------------------------------------------------------------------------
__global__ void __launch_bounds__(128, 1)
lpc_red_kernel(const float* __restrict__ ex,
               const float* __restrict__ gain,
               const float* __restrict__ a,
               float* __restrict__ out) {
    __shared__ float bufs[4][32 * 34];   // per-warp x stage AND y tile (in place)

    const int warp = threadIdx.x >> 5;
    const int lane = threadIdx.x & 31;
    const int gw   = blockIdx.x * 4 + warp;    // frame group 0..511
    const int s0   = gw * 32;
    const int s    = s0 + lane;                 // this lane's sequence
    const int b    = s >> 10;
    const int ww   = gw & 31;                   // group index within batch
    const int f0   = ww * 32;                   // base frame
    const bool edge = (ww == 0) || (ww == 31);  // only groups with o out of range

    float* __restrict__ buf = bufs[warp];

    const float g = gain[s];

    // c[q] = -a[q-1] (q=1..22), c[23]=c[24]=0
    float c[25];
    #pragma unroll
    for (int p = 0; p < Pn; ++p) c[p + 1] = -a[s * Pn + p];
    c[23] = 0.0f; c[24] = 0.0f;
    const float c1 = c[1];

    // CA[k] = (c_{2k+1}, c_{2k+2}) : y-even dot
    // CE[k] = (c_{2k+2}, c_{2k+3}) : y-odd shifted dot (y1 = c1*y0 + g*x1 + dotE)
    ull CA[11], CE[11], H[11];
    #pragma unroll
    for (int k = 0; k < 11; ++k) {
        CA[k] = pk2(c[2 * k + 1], c[2 * k + 2]);
        CE[k] = pk2(c[2 * k + 2], c[2 * k + 3]);
        H[k]  = 0ull;
    }

    const float* __restrict__ exb = ex + b * Tn;

    // prefetch chunk 0 (coalesced: lane sweeps time, r sweeps frames)
    float xr[32];
    #pragma unroll
    for (int r = 0; r < 32; ++r) {
        int idx = (f0 + r) * HOP + lane - PADL;
        xr[r] = ((unsigned)idx < (unsigned)Tn) ? exb[idx] : 0.0f;
    }

    for (int cc = 0; cc < NCHUNK; ++cc) {
        const int t0 = 32 * cc;

        // commit prefetched chunk to the buffer [seq row][time col]
        #pragma unroll
        for (int r = 0; r < 32; ++r) buf[r * 34 + lane] = xr[r];
        __syncwarp();

        // prefetch next chunk; latency hides under recurrence
        if (cc < NCHUNK - 1) {
            const int t1 = t0 + 32;
            #pragma unroll
            for (int r = 0; r < 32; ++r) {
                int idx = (f0 + r) * HOP + t1 + lane - PADL;
                xr[r] = ((unsigned)idx < (unsigned)Tn) ? exb[idx] : 0.0f;
            }
        }

        // 8 pairs x (2 blocks x 2 samples); buf row consumed/overwritten in place
        float* xrow = buf + lane * 34;
        #pragma unroll
        for (int bp = 0; bp < 8; ++bp) {
            const float2 xa = *(const float2*)(xrow + 4 * bp);
            const float2 xb = *(const float2*)(xrow + 4 * bp + 2);

            // ---- block A: dots over H[0..10], H[0] last ----
            ull ae = mul2_(CA[10], H[10]);
            ae = fma2_(CA[8], H[8], ae);
            ae = fma2_(CA[6], H[6], ae);
            ae = fma2_(CA[4], H[4], ae);
            ae = fma2_(CA[2], H[2], ae);
            ull ao = mul2_(CA[9], H[9]);
            ao = fma2_(CA[7], H[7], ao);
            ao = fma2_(CA[5], H[5], ao);
            ao = fma2_(CA[3], H[3], ao);
            ao = fma2_(CA[1], H[1], ao);
            ae = fma2_(CA[0], H[0], ae);
            const ull dA0 = add2_(ae, ao);

            ull ee = mul2_(CE[10], H[10]);
            ee = fma2_(CE[8], H[8], ee);
            ee = fma2_(CE[6], H[6], ee);
            ee = fma2_(CE[4], H[4], ee);
            ee = fma2_(CE[2], H[2], ee);
            ull eo = mul2_(CE[9], H[9]);
            eo = fma2_(CE[7], H[7], eo);
            eo = fma2_(CE[5], H[5], eo);
            eo = fma2_(CE[3], H[3], eo);
            eo = fma2_(CE[1], H[1], eo);
            ee = fma2_(CE[0], H[0], ee);
            const ull dE0 = add2_(ee, eo);

            float aLo, aHi, eLo, eHi;
            upk2(aLo, aHi, dA0);
            upk2(eLo, eHi, dE0);
            const float y0 = fmaf(g, xa.x, aLo + aHi);
            const float y1 = fmaf(c1, y0, fmaf(g, xa.y, eLo + eHi));
            const ull P = pk2(y1, y0);
            *(float2*)(xrow + 4 * bp) = make_float2(y0, y1);

            // ---- block B: dots over (P, H[0..9]); CA[k]*H[k-1], CA[0]*P last ----
            ull be = mul2_(CA[10], H[9]);
            be = fma2_(CA[8], H[7], be);
            be = fma2_(CA[6], H[5], be);
            be = fma2_(CA[4], H[3], be);
            be = fma2_(CA[2], H[1], be);
            ull bo = mul2_(CA[9], H[8]);
            bo = fma2_(CA[7], H[6], bo);
            bo = fma2_(CA[5], H[4], bo);
            bo = fma2_(CA[3], H[2], bo);
            bo = fma2_(CA[1], H[0], bo);
            be = fma2_(CA[0], P, be);
            const ull dA1 = add2_(be, bo);

            ull fe = mul2_(CE[10], H[9]);
            fe = fma2_(CE[8], H[7], fe);
            fe = fma2_(CE[6], H[5], fe);
            fe = fma2_(CE[4], H[3], fe);
            fe = fma2_(CE[2], H[1], fe);
            ull fo = mul2_(CE[9], H[8]);
            fo = fma2_(CE[7], H[6], fo);
            fo = fma2_(CE[5], H[4], fo);
            fo = fma2_(CE[3], H[2], fo);
            fo = fma2_(CE[1], H[0], fo);
            fe = fma2_(CE[0], P, fe);
            const ull dE1 = add2_(fe, fo);

            float aLo1, aHi1, eLo1, eHi1;
            upk2(aLo1, aHi1, dA1);
            upk2(eLo1, eHi1, dE1);
            const float y2 = fmaf(g, xb.x, aLo1 + aHi1);
            const float y3 = fmaf(c1, y2, fmaf(g, xb.y, eLo1 + eHi1));
            *(float2*)(xrow + 4 * bp + 2) = make_float2(y2, y3);

            // shift history by two pairs (9 MOV64 vs 20 for two single shifts)
            #pragma unroll
            for (int k = 10; k >= 2; --k) H[k] = H[k - 2];
            H[1] = P;
            H[0] = pk2(y3, y2);
        }
        __syncwarp();

        // emission: RED 0.5*w(t)*y into out (coalesced; addresses distinct)
        const float wv = 0.5f * hannf(t0 + lane);
        float* __restrict__ ob =
            out + (size_t)b * Tn + f0 * HOP + t0 + lane - PADL;
        if (!edge) {
            #pragma unroll
            for (int r = 0; r < 32; ++r)
                redadd(ob + r * HOP, buf[r * 34 + lane] * wv);
        } else {
            const int obase = f0 * HOP + t0 + lane - PADL;
            #pragma unroll
            for (int r = 0; r < 32; ++r) {
                const int o = obase + r * HOP;
                if ((unsigned)o < (unsigned)Tn)
                    redadd(ob + r * HOP, buf[r * 34 + lane] * wv);
            }
        }
        __syncwarp();
    }
}

// ---------------------------------------------------------------------------
// Kernel 2: edge normalization. Interior norm is exactly 2 (already folded as
//   x0.5 in emission); only the first 384 and last 384 samples of each batch
//   have norm != 2 -> rescale by 2/norm. 16 blocks x 768 threads.
// ---------------------------------------------------------------------------
__global__ void __launch_bounds__(768)
edgefix_kernel(float* __restrict__ out) {
    const int b = blockIdx.x;
    const int j = threadIdx.x;                 // 0..767
    const int o = (j < 384) ? j : (Tn - 768 + j);
    const int p = o + PADL;                    // batch-local padded coordinate

    const int fhi = p >> 8;
    float norm = 0.0f;
    #pragma unroll
    for (int k = 0; k < 4; ++k) {
        const int ff = fhi - k;
        if (ff >= 0 && ff < Fn) norm += hannf(p - ff * HOP);
    }
    float* q = out + (size_t)b * Tn + o;
    *q = (*q) * (2.0f / norm);
}

// ---------------------------------------------------------------------------
extern "C" void kernel_launch(void* const* d_in, const int* in_sizes, int n_in,
                              void* d_out, int out_size) {
    const float* ex   = (const float*)d_in[0];
    const float* gain = (const float*)d_in[1];
    const float* a    = (const float*)d_in[2];
    float* out = (float*)d_out;

    zero_kernel<<<(Bn * Tn / 4 + 255) / 256, 256>>>(out);
    lpc_red_kernel<<<128, 128>>>(ex, gain, a, out);
    edgefix_kernel<<<Bn, 768>>>(out);
}

// round 17
// speedup vs baseline: 1.0756x; 1.0756x over previous
#include <cuda_runtime.h>

#define Bn   16
#define Tn   262144
#define HOP  256
#define WINL 1024
#define PADL 384
#define Fn   1024
#define Pn   22
#define NGRP 512            // frame groups (32 frames each)
#define SPAN 8960           // per-group OLA span
#define STRIPL 768          // seam width
#define NCHUNK 20           // chunks per warp (offsets 0 / 384)
#define EMIT1  8            // warp1 emits from chunk 8 (256-sample warm-up)

// Cross-group seam halves + ticket counters (zero-init; self-resetting)
__device__ float d_strip_lo[NGRP][STRIPL];
__device__ float d_strip_hi[NGRP][STRIPL];
__device__ int   d_cnt[NGRP];

typedef unsigned long long ull;

static __device__ __forceinline__ ull pk2(float lo, float hi) {
    ull r; asm("mov.b64 %0,{%1,%2};" : "=l"(r) : "f"(lo), "f"(hi)); return r;
}
static __device__ __forceinline__ void upk2(float& lo, float& hi, ull v) {
    asm("mov.b64 {%0,%1},%2;" : "=f"(lo), "=f"(hi) : "l"(v));
}
static __device__ __forceinline__ ull fma2_(ull a, ull b, ull c) {
    ull r; asm("fma.rn.f32x2 %0,%1,%2,%3;" : "=l"(r) : "l"(a), "l"(b), "l"(c)); return r;
}
static __device__ __forceinline__ ull mul2_(ull a, ull b) {
    ull r; asm("mul.rn.f32x2 %0,%1,%2;" : "=l"(r) : "l"(a), "l"(b)); return r;
}
static __device__ __forceinline__ ull add2_(ull a, ull b) {
    ull r; asm("add.rn.f32x2 %0,%1,%2;" : "=l"(r) : "l"(a), "l"(b)); return r;
}

static __device__ __forceinline__ float hannf(int t) {
    return 0.5f - 0.5f * __cosf(6.283185307179586f * (float)t * (1.0f / 1024.0f));
}

// smem (floats): acc[SPAN] | buf[2 warps][32*34]  (buf = x stage AND y tile)
#define BUF_F (32 * 34)
#define SMEM_FLOATS (SPAN + 2 * BUF_F)
#define SMEM_BYTES  (SMEM_FLOATS * 4)   // 44544 B

// ---------------------------------------------------------------------------
// Kernel: one CTA (64 threads = 2 warps) per 32-frame group — R6 geometry.
//   warp0: computes t [0,640),    emits [0,640)
//   warp1: computes t [384,1024), emits [640,1024) (256-sample warm-up)
//   RACE PROOF: an acc collision requires OLA round-skew ≡ ±4 (mod 8).
//   Warp1 emits only from round 8; __syncthreads at end of rounds 7/11/15
//   bounds concurrent skew to <4 in every both-emitting window -> impossible.
//   Epilogue: interior written directly (norm == 2); interior seams resolved
//   in-kernel via global strips + atomic tickets (2nd arriver sums, writes,
//   resets the counter); batch edges normalized inline with hann norms.
// ---------------------------------------------------------------------------
__global__ void __launch_bounds__(64)
lpc_ola_kernel(const float* __restrict__ ex,
               const float* __restrict__ gain,
               const float* __restrict__ a,
               float* __restrict__ out) {
    extern __shared__ float smem[];

    const int warp = threadIdx.x >> 5;        // segment 0..1
    const int lane = threadIdx.x & 31;
    const int gw   = blockIdx.x;               // frame group 0..511
    const int s0   = gw * 32;
    const int s    = s0 + lane;                 // this lane's sequence
    const int b    = s >> 10;
    const int ww   = gw & 31;                   // group index within batch
    const int f0   = ww * 32;                   // base frame

    float* __restrict__ acc = smem;
    float* __restrict__ buf = smem + SPAN + warp * BUF_F;

    // zero shared accumulator
    for (int i = threadIdx.x; i < SPAN / 4; i += 64)
        ((float4*)acc)[i] = make_float4(0.f, 0.f, 0.f, 0.f);

    const float g = gain[s];

    // c[q] = -a[q-1] (q=1..22), c[23]=c[24]=0
    float c[25];
    #pragma unroll
    for (int p = 0; p < Pn; ++p) c[p + 1] = -a[s * Pn + p];
    c[23] = 0.0f; c[24] = 0.0f;
    const float c1 = c[1];

    // CA[k] = (c_{2k+1}, c_{2k+2}) : y0 dot
    // CE[k] = (c_{2k+2}, c_{2k+3}) : y1 shifted dot (y1 = c1*y0 + g*x1 + dotE)
    ull CA[11], CE[11], H[11];
    #pragma unroll
    for (int k = 0; k < 11; ++k) {
        CA[k] = pk2(c[2 * k + 1], c[2 * k + 2]);
        CE[k] = pk2(c[2 * k + 2], c[2 * k + 3]);
        H[k]  = 0ull;
    }
    __syncthreads();

    const float* __restrict__ exb = ex + b * Tn;
    const int tbase = warp ? 384 : 0;
    const int emit0 = warp ? EMIT1 : 0;

    // prefetch chunk 0 (coalesced: lane sweeps time, r sweeps frames)
    float xr[32];
    #pragma unroll
    for (int r = 0; r < 32; ++r) {
        int idx = (f0 + r) * HOP + tbase + lane - PADL;
        xr[r] = ((unsigned)idx < (unsigned)Tn) ? exb[idx] : 0.0f;
    }

    for (int cc = 0; cc < NCHUNK; ++cc) {
        const int t0 = tbase + 32 * cc;

        // commit prefetched chunk to this warp's buffer
        #pragma unroll
        for (int r = 0; r < 32; ++r) buf[r * 34 + lane] = xr[r];
        __syncwarp();

        // prefetch next chunk; latency hides under recurrence
        if (cc < NCHUNK - 1) {
            const int t1 = t0 + 32;
            #pragma unroll
            for (int r = 0; r < 32; ++r) {
                int idx = (f0 + r) * HOP + t1 + lane - PADL;
                xr[r] = ((unsigned)idx < (unsigned)Tn) ? exb[idx] : 0.0f;
            }
        }

        // 16 blocks x 2 samples; buf row consumed and overwritten in place
        float* xrow = buf + lane * 34;
        float2 xp2 = *(const float2*)xrow;
        #pragma unroll
        for (int bk = 0; bk < 16; ++bk) {
            float2 xn2;
            if (bk < 15) xn2 = *(const float2*)(xrow + 2 * bk + 2);
            const float x0 = xp2.x, x1 = xp2.y;

            // even/odd split packed dots, H[0] last
            ull ae = mul2_(CA[10], H[10]);
            ae = fma2_(CA[8], H[8], ae);
            ae = fma2_(CA[6], H[6], ae);
            ae = fma2_(CA[4], H[4], ae);
            ae = fma2_(CA[2], H[2], ae);
            ull ao = mul2_(CA[9], H[9]);
            ao = fma2_(CA[7], H[7], ao);
            ao = fma2_(CA[5], H[5], ao);
            ao = fma2_(CA[3], H[3], ao);
            ao = fma2_(CA[1], H[1], ao);
            ae = fma2_(CA[0], H[0], ae);
            const ull accA = add2_(ae, ao);

            ull ee = mul2_(CE[10], H[10]);
            ee = fma2_(CE[8], H[8], ee);
            ee = fma2_(CE[6], H[6], ee);
            ee = fma2_(CE[4], H[4], ee);
            ee = fma2_(CE[2], H[2], ee);
            ull eo = mul2_(CE[9], H[9]);
            eo = fma2_(CE[7], H[7], eo);
            eo = fma2_(CE[5], H[5], eo);
            eo = fma2_(CE[3], H[3], eo);
            eo = fma2_(CE[1], H[1], eo);
            ee = fma2_(CE[0], H[0], ee);
            const ull accE = add2_(ee, eo);

            float aLo, aHi, eLo, eHi;
            upk2(aLo, aHi, accA);
            upk2(eLo, eHi, accE);
            const float y0 = fmaf(g, x0, aLo + aHi);
            const float y1 = fmaf(c1, y0, fmaf(g, x1, eLo + eHi));

            *(float2*)(xrow + 2 * bk) = make_float2(y0, y1);

            #pragma unroll
            for (int k = 10; k > 0; --k) H[k] = H[k - 1];
            H[0] = pk2(y1, y0);

            xp2 = xn2;
        }
        __syncwarp();

        // per-warp windowed OLA accumulate (emit range only)
        if (cc >= emit0) {
            const float wv = hannf(t0 + lane);
            #pragma unroll
            for (int r = 0; r < 32; ++r)
                acc[r * HOP + t0 + lane] += buf[r * 34 + lane] * wv;
        }
        __syncwarp();

        // skew bound: collisions need skew >= 4; these 3 barriers keep
        // concurrent skew < 4 in every window where both warps emit
        if (cc == 7 || cc == 11 || cc == 15) __syncthreads();
    }
    __syncthreads();

    // ---- epilogue ----
    // interior [768, 8192): all 4 contributions local; norm == 2 exactly
    float* __restrict__ outb = out + (size_t)b * Tn + ww * 8192 + 384;
    const float4* __restrict__ acc4 = (const float4*)(acc + STRIPL);
    for (int i = threadIdx.x; i < (8192 - STRIPL) / 4; i += 64) {
        float4 v = acc4[i];
        v.x *= 0.5f; v.y *= 0.5f; v.z *= 0.5f; v.w *= 0.5f;
        ((float4*)outb)[i] = v;
    }

    if (warp == 0) {
        // lo strip: padded p = ww*8192 + j
        if (ww == 0) {
            // batch-leading edge: single contributor, hann norms
            for (int j = lane; j < STRIPL; j += 32) {
                const int o = j - PADL;
                if ((unsigned)o >= (unsigned)Tn) continue;
                const int fhi = j >> 8;
                float norm = 0.0f;
                #pragma unroll
                for (int k = 0; k < 4; ++k) {
                    const int ff = fhi - k;
                    if (ff >= 0 && ff < Fn) norm += hannf(j - ff * HOP);
                }
                out[(size_t)b * Tn + o] = acc[j] / norm;
            }
        } else {
            for (int j = lane; j < STRIPL; j += 32)
                __stcg(&d_strip_lo[gw][j], acc[j]);
            __threadfence();
            int old = 0;
            if (lane == 0) old = atomicAdd(&d_cnt[gw], 1);
            old = __shfl_sync(0xffffffffu, old, 0);
            if (old == 1) {   // second arriver resolves seam gw (norm == 2)
                __threadfence();
                for (int j = lane; j < STRIPL; j += 32) {
                    const float v = __ldcg(&d_strip_lo[gw][j]) +
                                    __ldcg(&d_strip_hi[gw - 1][j]);
                    out[(size_t)b * Tn + ww * 8192 + j - PADL] = v * 0.5f;
                }
                if (lane == 0) d_cnt[gw] = 0;   // self-reset for graph replay
            }
        }
    } else {
        // hi strip: padded p = (ww+1)*8192 + j
        if (ww == 31) {
            // batch-trailing edge: single contributor, hann norms (j < 384)
            for (int j = lane; j < 384; j += 32) {
                const int p = 32 * 8192 + j;
                const int o = p - PADL;           // in [261760, 262144)
                const int fhi = p >> 8;
                float norm = 0.0f;
                #pragma unroll
                for (int k = 0; k < 4; ++k) {
                    const int ff = fhi - k;
                    if (ff >= 0 && ff < Fn) norm += hannf(p - ff * HOP);
                }
                out[(size_t)b * Tn + o] = acc[8192 + j] / norm;
            }
        } else {
            for (int j = lane; j < STRIPL; j += 32)
                __stcg(&d_strip_hi[gw][j], acc[8192 + j]);
            __threadfence();
            int old = 0;
            if (lane == 0) old = atomicAdd(&d_cnt[gw + 1], 1);
            old = __shfl_sync(0xffffffffu, old, 0);
            if (old == 1) {   // second arriver resolves seam gw+1 (norm == 2)
                __threadfence();
                for (int j = lane; j < STRIPL; j += 32) {
                    const float v = __ldcg(&d_strip_lo[gw + 1][j]) +
                                    __ldcg(&d_strip_hi[gw][j]);
                    out[(size_t)b * Tn + (ww + 1) * 8192 + j - PADL] = v * 0.5f;
                }
                if (lane == 0) d_cnt[gw + 1] = 0;
            }
        }
    }
}

// ---------------------------------------------------------------------------
extern "C" void kernel_launch(void* const* d_in, const int* in_sizes, int n_in,
                              void* d_out, int out_size) {
    const float* ex   = (const float*)d_in[0];
    const float* gain = (const float*)d_in[1];
    const float* a    = (const float*)d_in[2];
    float* out = (float*)d_out;

    cudaFuncSetAttribute(lpc_ola_kernel,
                         cudaFuncAttributeMaxDynamicSharedMemorySize, SMEM_BYTES);
    lpc_ola_kernel<<<NGRP, 64, SMEM_BYTES>>>(ex, gain, a, out);
}